// round 5
// baseline (speedup 1.0000x reference)
#include <cuda_runtime.h>

// SelMul: out[b, k] = x[b, i] * x[b, j] for upper-triangular (i<=j), row-major.
// x: (256, 1024) fp32 -> out: (256, 524800) fp32 (~537 MB). Pure store-bound.
//
// Grid mapping: block (i, b) writes the contiguous segment for source row index i:
//   base = b*TRI + i*N - i*(i-1)/2, length N-i, element j' stores x[b,i]*x[b,i+j'].
// All stores coalesced; streaming (.cs) since output is write-once.

static constexpr int N   = 1024;
static constexpr int B   = 256;
static constexpr int TRI = N * (N + 1) / 2;  // 524800

__global__ __launch_bounds__(256, 8)
void selmul_kernel(const float* __restrict__ x, float* __restrict__ out) {
    const int i = blockIdx.x;          // 0..N-1  (source column index / triangle row)
    const int b = blockIdx.y;          // 0..B-1

    const float* __restrict__ xrow = x + b * N;
    const float xi = __ldg(xrow + i);

    // Segment base within the full output. Max index 256*524800-1 < 2^31 -> int ok.
    const int base = b * TRI + i * N - (i * (i - 1)) / 2;
    const int len  = N - i;

    // Coalesced streaming stores of the contiguous segment.
    for (int j = threadIdx.x; j < len; j += blockDim.x) {
        const float v = xi * __ldg(xrow + i + j);
        __stcs(out + base + j, v);
    }
}

extern "C" void kernel_launch(void* const* d_in, const int* in_sizes, int n_in,
                              void* d_out, int out_size) {
    (void)in_sizes; (void)n_in; (void)out_size;
    const float* x = (const float*)d_in[0];
    float* out = (float*)d_out;

    dim3 grid(N, B);   // 1024 x 256 blocks
    dim3 block(256);
    selmul_kernel<<<grid, block>>>(x, out);
}

// round 6
// speedup vs baseline: 1.1619x; 1.1619x over previous
#include <cuda_runtime.h>

// SelMul: out[b, k] = x[b,i] * x[b,j] for i<=j, row-major triangular order.
// x: (256,1024) fp32 -> out: (256,524800) fp32 (~537 MB written). Store-bound.
//
// R5 redesign vs R4 (204.8us, DRAM 26.6%, bound by CTA/wave overhead of 262K
// tiny blocks):
//  - Pair-balanced fat blocks: pair p handles segments i=p (len N-p) and
//    i=N-1-p (len p+1) -> exactly N+1 elements per pair, for BB=16 batches.
//    Grid = 512 x 16 = 8192 CTAs (~7 waves), perfectly load-balanced.
//  - Row staged in SMEM once per batch; body loads are conflict-free LDS.128
//    with compile-time shift select (no dynamic local-array indexing).
//  - Stores: scalar head to 16B-align, then STG.128 streaming (__stcs).

static constexpr int N       = 1024;
static constexpr int B       = 256;
static constexpr int TRI     = N * (N + 1) / 2;    // 524800
static constexpr int BB      = 16;                 // batches per block
static constexpr int THREADS = 256;

// Body loop specialized on load misalignment A = (i + head) & 3.
// Loads two consecutive aligned float4s and selects the window at shift A.
template <int A>
__device__ __forceinline__ void body_loop(const float4* __restrict__ srow4,
                                          int qbase, int nvec,
                                          float xi, float4* __restrict__ op4) {
    for (int v = threadIdx.x; v < nvec; v += THREADS) {
        float4 f0 = srow4[qbase + v];
        float4 r;
        if constexpr (A == 0) {
            r.x = f0.x; r.y = f0.y; r.z = f0.z; r.w = f0.w;
        } else {
            float4 f1 = srow4[qbase + v + 1];
            if constexpr (A == 1) { r.x = f0.y; r.y = f0.z; r.z = f0.w; r.w = f1.x; }
            if constexpr (A == 2) { r.x = f0.z; r.y = f0.w; r.z = f1.x; r.w = f1.y; }
            if constexpr (A == 3) { r.x = f0.w; r.y = f1.x; r.z = f1.y; r.w = f1.z; }
        }
        r.x *= xi; r.y *= xi; r.z *= xi; r.w *= xi;
        __stcs(op4 + v, r);
    }
}

__global__ __launch_bounds__(THREADS, 8)
void selmul_kernel(const float* __restrict__ x, float* __restrict__ out) {
    // +1 float4 pad: shifted body loads may touch one float4 past the row.
    __shared__ float4 srow4[N / 4 + 1];
    float* srow = reinterpret_cast<float*>(srow4);

    const int p  = blockIdx.x;            // 0..511 (segment pair)
    const int b0 = blockIdx.y * BB;
    const int i0 = p;                     // long segment (len N-p)
    const int i1 = N - 1 - p;             // mirror segment (len p+1)

    for (int bb = 0; bb < BB; ++bb) {
        const int b = b0 + bb;

        // Stage row b (4 KB) into SMEM with aligned float4 loads.
        const float4* xr4 = reinterpret_cast<const float4*>(x + b * N);
        for (int t = threadIdx.x; t < N / 4; t += THREADS)
            srow4[t] = xr4[t];
        __syncthreads();

        #pragma unroll
        for (int s = 0; s < 2; ++s) {
            const int i   = s ? i1 : i0;
            const int len = N - i;
            const float xi = srow[i];
            // base fits in int: max = 256*524800 - 1 < 2^31.
            const int base = b * TRI + i * N - (i * (i - 1)) / 2;
            float* op = out + base;

            // Scalar head until store pointer is 16B-aligned.
            int head = (4 - (base & 3)) & 3;
            if (head > len) head = len;
            for (int j = threadIdx.x; j < head; j += THREADS)
                __stcs(op + j, xi * srow[i + j]);

            const int nvec  = (len - head) >> 2;
            float4* op4     = reinterpret_cast<float4*>(op + head);
            const int qbase = (i + head) >> 2;
            switch ((i + head) & 3) {
                case 0: body_loop<0>(srow4, qbase, nvec, xi, op4); break;
                case 1: body_loop<1>(srow4, qbase, nvec, xi, op4); break;
                case 2: body_loop<2>(srow4, qbase, nvec, xi, op4); break;
                default: body_loop<3>(srow4, qbase, nvec, xi, op4); break;
            }

            // Scalar tail.
            for (int j = head + 4 * nvec + threadIdx.x; j < len; j += THREADS)
                __stcs(op + j, xi * srow[i + j]);
        }
        __syncthreads();   // all reads done before restaging next row
    }
}

extern "C" void kernel_launch(void* const* d_in, const int* in_sizes, int n_in,
                              void* d_out, int out_size) {
    (void)in_sizes; (void)n_in; (void)out_size;
    const float* x = (const float*)d_in[0];
    float* out = (float*)d_out;

    dim3 grid(N / 2, B / BB);   // 512 x 16 = 8192 blocks
    dim3 block(THREADS);
    selmul_kernel<<<grid, block>>>(x, out);
}

// round 9
// speedup vs baseline: 2.1245x; 1.8284x over previous
#include <cuda_runtime.h>

// SelMul: pair (i,j), i<=j, row-major triangular:
//   offset(i,j) = i*N - T(i+1) + j,  T(k) = k(k-1)/2,  value x[b,i]*x[b,j].
// x: (256,1024) fp32 -> out: (256,524800) fp32 (~537 MB). Store-bound.
//
// R8 = R7 octet register tiling with the base fixed to i*N - T(i+1)
// (R6/R7 stored at i*N - T(i) + j: off by +i -> rel_err ~ sqrt(2)).
//
// Octet = rows i0..i0+7, i0 % 8 == 0. Aligned store needs j == T(i+1) (mod 4);
// for i0%8==0, T(i0+r+1) == T(r+1) (mod 4). First aligned j = i0 + D(r),
//   D(r) = r + ((T(r+1)&3 - r) & 3) = {0,1,3,6,6,7,9,8},  max D+3 = 12.
// Window t: w[0..15] = x[i0+4t .. i0+4t+15] (4 aligned LDG.128, clamped
// overfetch only feeds predicated-off lanes); row r emits one aligned STG.128
// covering j = i0+D+4t..+3 with value w[D..D+3]*x[i0+r].
// Heads [i, fj) and tails [fj+4n, N) (<=3+3 elems) by scalar threads 0..15
// using the same congruence -> exact coverage, no overlap.

static constexpr int N       = 1024;
static constexpr int B       = 256;
static constexpr int TRI     = N * (N + 1) / 2;   // 524800
static constexpr int BB      = 4;                 // batches per block
static constexpr int THREADS = 256;
static constexpr int M4LAST  = N / 4 - 1;         // 255

__host__ __device__ constexpr int triang(int k) { return k * (k - 1) / 2; }
__host__ __device__ constexpr int Dof(int r) {
    return r + ((((triang(r + 1) & 3) - r) + 8) & 3);
}

template <int K>
__device__ __forceinline__ float pick(const float4& a, const float4& b,
                                      const float4& c, const float4& d) {
    if constexpr (K == 0)  return a.x;
    else if constexpr (K == 1)  return a.y;
    else if constexpr (K == 2)  return a.z;
    else if constexpr (K == 3)  return a.w;
    else if constexpr (K == 4)  return b.x;
    else if constexpr (K == 5)  return b.y;
    else if constexpr (K == 6)  return b.z;
    else if constexpr (K == 7)  return b.w;
    else if constexpr (K == 8)  return c.x;
    else if constexpr (K == 9)  return c.y;
    else if constexpr (K == 10) return c.z;
    else if constexpr (K == 11) return c.w;
    else if constexpr (K == 12) return d.x;
    else if constexpr (K == 13) return d.y;
    else if constexpr (K == 14) return d.z;
    else return d.w;
}

template <int R>
__device__ __forceinline__ void octet_row(const float4& w0, const float4& w1,
                                          const float4& w2, const float4& w3,
                                          const float4& xq0, const float4& xq1,
                                          float* __restrict__ outb,
                                          int i0, int t) {
    constexpr int D = Dof(R);
    const int v = N - i0 - D;            // 4*n_r (may be <= 0 for last octet)
    if (v <= 0) return;
    if (t < (v >> 2)) {
        const int i = i0 + R;
        const float xi = pick<R>(xq0, xq1, xq1, xq1);       // x[i0+R]
        const int base = i * N - triang(i + 1);             // CORRECTED base
        float4 o;
        o.x = pick<D    >(w0, w1, w2, w3) * xi;
        o.y = pick<D + 1>(w0, w1, w2, w3) * xi;
        o.z = pick<D + 2>(w0, w1, w2, w3) * xi;
        o.w = pick<D + 3>(w0, w1, w2, w3) * xi;
        // (base + i0 + D) % 4 == 0 by construction -> aligned STG.128
        __stcs(reinterpret_cast<float4*>(outb + base + i0 + D) + t, o);
    }
}

__device__ __forceinline__ void octet(const float4* __restrict__ xr4,
                                      float* __restrict__ outb,
                                      int i0, int t) {
    const int nmax = (N - i0) >> 2;      // row r=0 has D=0 -> largest n
    if (t >= nmax) return;
    const int m = (i0 >> 2) + t;
    // Clamped overfetch: needed x index 4m+k (k<=15) <= N-1 implies the
    // containing word m + k/4 <= M4LAST, so clamps never feed active lanes.
    const float4 w0 = __ldg(xr4 + m);
    const float4 w1 = __ldg(xr4 + (m + 1 > M4LAST ? M4LAST : m + 1));
    const float4 w2 = __ldg(xr4 + (m + 2 > M4LAST ? M4LAST : m + 2));
    const float4 w3 = __ldg(xr4 + (m + 3 > M4LAST ? M4LAST : m + 3));
    const float4 xq0 = __ldg(xr4 + (i0 >> 2));       // x[i0..i0+3]
    const float4 xq1 = __ldg(xr4 + (i0 >> 2) + 1);   // x[i0+4..i0+7]
    octet_row<0>(w0, w1, w2, w3, xq0, xq1, outb, i0, t);
    octet_row<1>(w0, w1, w2, w3, xq0, xq1, outb, i0, t);
    octet_row<2>(w0, w1, w2, w3, xq0, xq1, outb, i0, t);
    octet_row<3>(w0, w1, w2, w3, xq0, xq1, outb, i0, t);
    octet_row<4>(w0, w1, w2, w3, xq0, xq1, outb, i0, t);
    octet_row<5>(w0, w1, w2, w3, xq0, xq1, outb, i0, t);
    octet_row<6>(w0, w1, w2, w3, xq0, xq1, outb, i0, t);
    octet_row<7>(w0, w1, w2, w3, xq0, xq1, outb, i0, t);
}

__global__ __launch_bounds__(THREADS)
void selmul_kernel(const float* __restrict__ x, float* __restrict__ out) {
    const int q   = blockIdx.x;        // 0..63
    const int i0A = 8 * q;             // 0..504
    const int i0B = 1016 - 8 * q;      // 1016..512  (both % 8 == 0)
    const int t   = threadIdx.x;
    const int tr  = THREADS - 1 - t;   // reversed lanes for the mirror octet:
                                       // activeA (from lane 0 up) + activeB
                                       // (from lane 255 down) ~ 258 lanes total
                                       // -> near-zero idle lanes at every q.

    for (int bb = 0; bb < BB; ++bb) {
        const int b = blockIdx.y * BB + bb;
        const float*  xrow = x + b * N;
        const float4* xr4  = reinterpret_cast<const float4*>(xrow);
        float* outb = out + b * TRI;   // max elem offset < 2^27: int-safe

        // Scalar heads + tails for the 16 rows of both octets (<= 6 elems each).
        if (t < 16) {
            const int i0 = (t & 8) ? i0B : i0A;
            const int i  = i0 + (t & 7);
            const int Tn = triang(i + 1);
            const int base = i * N - Tn;                       // CORRECTED base
            const int fj = i + ((((Tn & 3) - (i & 3)) + 4) & 3); // first aligned j
            const float xi = __ldg(xrow + i);
            const int he = fj < N ? fj : N;
            for (int j = i; j < he; ++j)
                __stcs(outb + base + j, xi * __ldg(xrow + j));
            const int nv = (N > fj) ? ((N - fj) >> 2) : 0;
            for (int j = fj + 4 * nv; j < N; ++j)
                __stcs(outb + base + j, xi * __ldg(xrow + j));
        }

        octet(xr4, outb, i0A, t);
        octet(xr4, outb, i0B, tr);
    }
}

extern "C" void kernel_launch(void* const* d_in, const int* in_sizes, int n_in,
                              void* d_out, int out_size) {
    (void)in_sizes; (void)n_in; (void)out_size;
    const float* x = (const float*)d_in[0];
    float* out = (float*)d_out;

    dim3 grid(N / 16, B / BB);   // 64 octet-pairs x 64 batch groups = 4096 blocks
    dim3 block(THREADS);
    selmul_kernel<<<grid, block>>>(x, out);
}